// round 8
// baseline (speedup 1.0000x reference)
#include <cuda_runtime.h>
#include <cuda_bf16.h>
#include <cstdint>

#define N_NODES 50000
#define N_EDGES 500000
#define HIDDEN  128
#define HEADS   8
#define HDIM    16

// ---------------- static device scratch ----------------
__device__ float g_q[N_NODES * HIDDEN];     // q
__device__ float g_k[N_NODES * HIDDEN];     // k; later reused as t1 (silu output)
__device__ float g_v[N_NODES * HIDDEN];
__device__ float g_ex[N_EDGES * HEADS];     // exp(logit) per (edge, head)
__device__ float g_s[N_NODES * HEADS];
__device__ float g_U[N_NODES * HIDDEN];
__device__ float g_disp[N_NODES * 3];

// ---------------- init ----------------
__global__ void k_init() {
    int i = blockIdx.x * blockDim.x + threadIdx.x;
    float4 z = make_float4(0.f, 0.f, 0.f, 0.f);
    if (i < N_NODES * HIDDEN / 4) ((float4*)g_U)[i] = z;
    if (i < N_NODES * HEADS / 4) ((float4*)g_s)[i] = z;
    if (i < N_NODES * 3 / 4) ((float4*)g_disp)[i] = z;
}

// ---------------- packed-f32x2 GEMM, software-pipelined ----------------
// C[M,128] = A[M,128] @ W[128,128] + bias (+res / silu). 128x128 CTA tile,
// 256 thr, 8x8 microtile, fma.rn.f32x2 inner loop, register-staged gmem loads.
#define KC 16

__device__ __forceinline__ uint64_t pack_dup(float a) {
    uint64_t r;
    asm("mov.b64 %0, {%1, %1};" : "=l"(r) : "f"(a));
    return r;
}
__device__ __forceinline__ void fma2(uint64_t& c, uint64_t a, uint64_t b) {
    asm("fma.rn.f32x2 %0, %1, %2, %0;" : "+l"(c) : "l"(a), "l"(b));
}
__device__ __forceinline__ float2 unpack2(uint64_t p) {
    float lo, hi;
    asm("mov.b64 {%0, %1}, %2;" : "=f"(lo), "=f"(hi) : "l"(p));
    return make_float2(lo, hi);
}

template <int EPI, bool SCALE_A>
__global__ __launch_bounds__(256, 2) void gemm128(
    const float* __restrict__ A,
    const float* __restrict__ B0, const float* __restrict__ B1, const float* __restrict__ B2,
    const float* __restrict__ bias0, const float* __restrict__ bias1, const float* __restrict__ bias2,
    const float* __restrict__ res,
    float* __restrict__ out0, float* __restrict__ out1, float* __restrict__ out2,
    int M)
{
    __shared__ float As[KC][132];     // transposed: As[k][m]
    __shared__ float Bs[KC][HIDDEN];

    const float* B    = (blockIdx.y == 0) ? B0    : (blockIdx.y == 1) ? B1    : B2;
    const float* bias = (blockIdx.y == 0) ? bias0 : (blockIdx.y == 1) ? bias1 : bias2;
    float*       out  = (blockIdx.y == 0) ? out0  : (blockIdx.y == 1) ? out1  : out2;

    const int t   = threadIdx.x;
    const int tx  = t & 15;           // col group (8 cols = 4 packed pairs)
    const int ty  = t >> 4;           // row group (8 rows)
    const int row0 = blockIdx.x * 128;

    // staging indices (fixed per thread)
    const int ar0 = t >> 2,        ac0 = (t & 3) * 4;         // A: rows t/4, t/4+64? no: idx, idx+256
    const int ar1 = (t + 256) >> 2, ac1 = ((t + 256) & 3) * 4;
    const int br0 = t >> 5,        bc0 = (t & 31) * 4;
    const int br1 = (t + 256) >> 5, bc1 = ((t + 256) & 31) * 4;

    float4 sa0, sa1, sb0, sb1;        // staged next-chunk values

    auto load_chunk = [&](int kt) {
        sa0 = make_float4(0.f, 0.f, 0.f, 0.f);
        sa1 = make_float4(0.f, 0.f, 0.f, 0.f);
        int gr0 = row0 + ar0, gr1 = row0 + ar1;
        if (gr0 < M) {
            sa0 = *(const float4*)(A + gr0 * HIDDEN + kt + ac0);
            if (SCALE_A) {
                float inv = __frcp_rn(fmaxf(g_s[gr0 * HEADS + ((kt + ac0) >> 4)], 1e-9f));
                sa0.x *= inv; sa0.y *= inv; sa0.z *= inv; sa0.w *= inv;
            }
        }
        if (gr1 < M) {
            sa1 = *(const float4*)(A + gr1 * HIDDEN + kt + ac1);
            if (SCALE_A) {
                float inv = __frcp_rn(fmaxf(g_s[gr1 * HEADS + ((kt + ac1) >> 4)], 1e-9f));
                sa1.x *= inv; sa1.y *= inv; sa1.z *= inv; sa1.w *= inv;
            }
        }
        sb0 = *(const float4*)(B + (kt + br0) * HIDDEN + bc0);
        sb1 = *(const float4*)(B + (kt + br1) * HIDDEN + bc1);
    };
    auto store_chunk = [&]() {
        As[ac0 + 0][ar0] = sa0.x; As[ac0 + 1][ar0] = sa0.y;
        As[ac0 + 2][ar0] = sa0.z; As[ac0 + 3][ar0] = sa0.w;
        As[ac1 + 0][ar1] = sa1.x; As[ac1 + 1][ar1] = sa1.y;
        As[ac1 + 2][ar1] = sa1.z; As[ac1 + 3][ar1] = sa1.w;
        *(float4*)(&Bs[br0][bc0]) = sb0;
        *(float4*)(&Bs[br1][bc1]) = sb1;
    };

    uint64_t acc[8][4];
#pragma unroll
    for (int i = 0; i < 8; i++)
#pragma unroll
        for (int j = 0; j < 4; j++) acc[i][j] = 0ull;

    load_chunk(0);
    store_chunk();

#pragma unroll
    for (int c = 0; c < HIDDEN / KC; c++) {
        __syncthreads();
        if (c + 1 < HIDDEN / KC) load_chunk((c + 1) * KC);   // overlaps compute below

#pragma unroll
        for (int kk = 0; kk < KC; kk++) {
            float4 a0 = *(float4*)(&As[kk][ty * 8]);
            float4 a1 = *(float4*)(&As[kk][ty * 8 + 4]);
            ulonglong2 b01 = *(ulonglong2*)(&Bs[kk][tx * 8]);
            ulonglong2 b23 = *(ulonglong2*)(&Bs[kk][tx * 8 + 4]);
            uint64_t bp[4] = {b01.x, b01.y, b23.x, b23.y};
            uint64_t ap[8];
            ap[0] = pack_dup(a0.x); ap[1] = pack_dup(a0.y);
            ap[2] = pack_dup(a0.z); ap[3] = pack_dup(a0.w);
            ap[4] = pack_dup(a1.x); ap[5] = pack_dup(a1.y);
            ap[6] = pack_dup(a1.z); ap[7] = pack_dup(a1.w);
#pragma unroll
            for (int i = 0; i < 8; i++)
#pragma unroll
                for (int j = 0; j < 4; j++) fma2(acc[i][j], ap[i], bp[j]);
        }
        __syncthreads();
        if (c + 1 < HIDDEN / KC) store_chunk();
    }

    // epilogue: 8 rows x 8 cols per thread
#pragma unroll
    for (int i = 0; i < 8; i++) {
        int gr = row0 + ty * 8 + i;
        if (gr >= M) continue;
#pragma unroll
        for (int jj = 0; jj < 2; jj++) {
            int col = tx * 8 + jj * 4;
            float2 p0 = unpack2(acc[i][jj * 2 + 0]);
            float2 p1 = unpack2(acc[i][jj * 2 + 1]);
            float z[4] = {p0.x, p0.y, p1.x, p1.y};
#pragma unroll
            for (int q = 0; q < 4; q++) z[q] += bias[col + q];
            if (EPI == 1) {
                float4 r4 = *(const float4*)(res + gr * HIDDEN + col);
                z[0] += r4.x; z[1] += r4.y; z[2] += r4.z; z[3] += r4.w;
            }
            if (EPI == 2) {
#pragma unroll
                for (int q = 0; q < 4; q++) z[q] = z[q] / (1.f + __expf(-z[q]));
            }
            *(float4*)(out + gr * HIDDEN + col) = make_float4(z[0], z[1], z[2], z[3]);
        }
    }
}

// ---------------- fused edge kernel: logits + exp + s-sum + U scatter ----------------
__global__ __launch_bounds__(512) void k_edge(
    const int* __restrict__ src, const int* __restrict__ dst,
    const float* __restrict__ dist,
    const float* __restrict__ Wd, const float* __restrict__ bd)
{
    int t = blockIdx.x * blockDim.x + threadIdx.x;
    if (t >= N_EDGES * HEADS) return;
    int e = t >> 3, h = t & 7;
    int sn = src[e], dn = dst[e];

    const float4* qp = (const float4*)(g_q + sn * HIDDEN + h * HDIM);
    const float4* kp = (const float4*)(g_k + dn * HIDDEN + h * HDIM);
    float acc = 0.f;
#pragma unroll
    for (int i = 0; i < 4; i++) {
        float4 a = qp[i], b = kp[i];
        acc += a.x * b.x + a.y * b.y + a.z * b.z + a.w * b.w;
    }
    float dd = dist[e];
    float lg = acc * 0.25f - (dd * dd * Wd[h] + bd[h]);
    float ex = __expf(lg);
    g_ex[t] = ex;

    atomicAdd(&g_s[sn * HEADS + h], ex);

    const float4* vp = (const float4*)(g_v + dn * HIDDEN + h * HDIM);
    float* up = g_U + sn * HIDDEN + h * HDIM;
#pragma unroll
    for (int i = 0; i < 4; i++) {
        float4 vv = vp[i];
        float x0 = vv.x * ex, x1 = vv.y * ex, x2 = vv.z * ex, x3 = vv.w * ex;
        asm volatile("red.global.add.v4.f32 [%0], {%1,%2,%3,%4};"
                     :: "l"(up + i * 4), "f"(x0), "f"(x1), "f"(x2), "f"(x3)
                     : "memory");
    }
}

// ---------------- displacement scatter ----------------
__global__ void k_disp(const int* __restrict__ src, const int* __restrict__ dst,
                       const float* __restrict__ x)
{
    int e = blockIdx.x * blockDim.x + threadIdx.x;
    if (e >= N_EDGES) return;
    int sn = src[e], dn = dst[e];

    const float4* exp4 = (const float4*)(g_ex + e * 8);
    const float4* sp   = (const float4*)(g_s + sn * 8);
    float4 e0 = exp4[0], e1 = exp4[1];
    float4 s0 = sp[0],   s1 = sp[1];

    float wsum =
        e0.x / fmaxf(s0.x, 1e-9f) + e0.y / fmaxf(s0.y, 1e-9f) +
        e0.z / fmaxf(s0.z, 1e-9f) + e0.w / fmaxf(s0.w, 1e-9f) +
        e1.x / fmaxf(s1.x, 1e-9f) + e1.y / fmaxf(s1.y, 1e-9f) +
        e1.z / fmaxf(s1.z, 1e-9f) + e1.w / fmaxf(s1.w, 1e-9f);
    float wmean = wsum * 0.125f;

#pragma unroll
    for (int c = 0; c < 3; c++)
        atomicAdd(&g_disp[sn * 3 + c], (x[dn * 3 + c] - x[sn * 3 + c]) * wmean);
}

// ---------------- gate + x_out ----------------
__global__ void k_gate(const float* __restrict__ Wg2, const float* __restrict__ bg2,
                       const float* __restrict__ x, float* __restrict__ out)
{
    int gt   = blockIdx.x * blockDim.x + threadIdx.x;
    int node = gt >> 5;
    int lane = threadIdx.x & 31;
    if (node >= N_NODES) return;

    float4 a = *(const float4*)(g_k + node * HIDDEN + lane * 4);  // t1
    float4 b = *(const float4*)(Wg2 + lane * 4);
    float p = a.x * b.x + a.y * b.y + a.z * b.z + a.w * b.w;
#pragma unroll
    for (int off = 16; off; off >>= 1) p += __shfl_xor_sync(0xffffffffu, p, off);
    float g = tanhf(p + bg2[0]);
    if (lane < 3) {
        out[N_NODES * HIDDEN + node * 3 + lane] =
            x[node * 3 + lane] + g * g_disp[node * 3 + lane];
    }
}

// ---------------- launch ----------------
extern "C" void kernel_launch(void* const* d_in, const int* in_sizes, int n_in,
                              void* d_out, int out_size)
{
    (void)in_sizes; (void)n_in; (void)out_size;
    const float* h    = (const float*)d_in[0];
    const float* x    = (const float*)d_in[1];
    const int*   src  = (const int*)  d_in[2];
    const int*   dst  = (const int*)  d_in[3];
    const float* dist = (const float*)d_in[4];
    const float* Wq = (const float*)d_in[5],  *bq = (const float*)d_in[6];
    const float* Wk = (const float*)d_in[7],  *bk = (const float*)d_in[8];
    const float* Wv = (const float*)d_in[9],  *bv = (const float*)d_in[10];
    const float* Wo = (const float*)d_in[11], *bo = (const float*)d_in[12];
    const float* Wd = (const float*)d_in[13], *bd = (const float*)d_in[14];
    const float* Wg1 = (const float*)d_in[15], *bg1 = (const float*)d_in[16];
    const float* Wg2 = (const float*)d_in[17], *bg2 = (const float*)d_in[18];
    float* out = (float*)d_out;

    void *pq, *pk, *pv, *pU;
    cudaGetSymbolAddress(&pq, g_q);
    cudaGetSymbolAddress(&pk, g_k);
    cudaGetSymbolAddress(&pv, g_v);
    cudaGetSymbolAddress(&pU, g_U);
    float* fq = (float*)pq; float* fk = (float*)pk; float* fv = (float*)pv;
    float* fU = (float*)pU;

    const int B = 256;
    k_init<<<(N_NODES * HIDDEN / 4 + B - 1) / B, B>>>();

    // fused QKV projection (FFMA2, pipelined)
    int gblocks = (N_NODES + 127) / 128;
    {
        dim3 grid(gblocks, 3);
        gemm128<0, false><<<grid, 256>>>(h, Wq, Wk, Wv, bq, bk, bv,
                                         nullptr, fq, fk, fv, N_NODES);
    }

    // edge phase (atomic scatter)
    int eht = N_EDGES * HEADS;
    k_edge<<<(eht + 511) / 512, 512>>>(src, dst, dist, Wd, bd);
    k_disp<<<(N_EDGES + B - 1) / B, B>>>(src, dst, x);

    // Wo GEMM normalizes g_U by rcp(s) on the fly
    {
        dim3 grid(gblocks, 1);
        gemm128<1, true><<<grid, 256>>>(fU, Wo, Wo, Wo, bo, bo, bo,
                                        h, out, out, out, N_NODES);
        gemm128<2, false><<<grid, 256>>>(out, Wg1, Wg1, Wg1, bg1, bg1, bg1,
                                         nullptr, fk, fk, fk, N_NODES);
    }
    k_gate<<<(N_NODES * 32 + B - 1) / B, B>>>(Wg2, bg2, x, out);
}